// round 7
// baseline (speedup 1.0000x reference)
#include <cuda_runtime.h>
#include <cstdint>

#define BATCH 8
#define SEQ   2048
#define DIM   1024

#define BM 128
#define BN 128
#define BK 16
#define TPB 256
#define LDA 132          // As row stride (floats)
#define LDB 260          // Bsd row stride (floats, duplicated values)
#define AS_FLOATS (2 * BK * LDA)          // 4224
#define BS_FLOATS (2 * BK * LDB)          // 8320
#define GEMM_SMEM ((AS_FLOATS + BS_FLOATS) * 4)   // 50176 bytes

typedef unsigned long long ull;

__device__ __forceinline__ void ffma2(ull& d, ull a, ull b) {
    asm("fma.rn.f32x2 %0, %1, %2, %0;" : "+l"(d) : "l"(a), "l"(b));
}
__device__ __forceinline__ ull dup2(float v) {
    ull r; asm("mov.b64 %0, {%1, %2};" : "=l"(r) : "f"(v), "f"(v)); return r;
}
__device__ __forceinline__ void unpk(ull p, float& lo, float& hi) {
    asm("mov.b64 {%0, %1}, %2;" : "=f"(lo), "=f"(hi) : "l"(p));
}

struct Acc {
    ull a[8][4];
};

// As: [BK][LDA] transposed A tile (row k, col m). Bsd: [BK][LDB] duplicated B.
__device__ __forceinline__ void compute_chunk(const float* __restrict__ As,
                                              const float* __restrict__ Bsd,
                                              int tm, int tn, Acc& acc) {
#pragma unroll
    for (int k = 0; k < BK; k++) {
        const float* ar = As + k * LDA;
        const float* br = Bsd + k * LDB;
        ulonglong2 a01 = *(const ulonglong2*)(ar + tm * 4);
        ulonglong2 a23 = *(const ulonglong2*)(ar + 64 + tm * 4);
        ulonglong2 b01 = *(const ulonglong2*)(br + 8 * tn);
        ulonglong2 b23 = *(const ulonglong2*)(br + 8 * tn + 4);
        ulonglong2 b45 = *(const ulonglong2*)(br + 128 + 8 * tn);
        ulonglong2 b67 = *(const ulonglong2*)(br + 128 + 8 * tn + 4);
        ull ap[4] = {a01.x, a01.y, a23.x, a23.y};
        ull bd[8] = {b01.x, b01.y, b23.x, b23.y, b45.x, b45.y, b67.x, b67.y};
#pragma unroll
        for (int v = 0; v < 8; v++)
#pragma unroll
            for (int p = 0; p < 4; p++) ffma2(acc.a[v][p], ap[p], bd[v]);
    }
}

__device__ __forceinline__ void store_tile(float* dst, size_t ld, int tm, int tn,
                                           const Acc& acc) {
#pragma unroll
    for (int u = 0; u < 8; u++) {
        const int p = u >> 1, hi = u & 1;
        const int r = (u < 4) ? (tm * 4 + u) : (64 + tm * 4 + (u - 4));
        float c[8];
#pragma unroll
        for (int v = 0; v < 8; v++) {
            float lo, hh;
            unpk(acc.a[v][p], lo, hh);
            c[v] = hi ? hh : lo;
        }
        *(float4*)&dst[(size_t)r * ld + tn * 4]      = make_float4(c[0], c[1], c[2], c[3]);
        *(float4*)&dst[(size_t)r * ld + 64 + tn * 4] = make_float4(c[4], c[5], c[6], c[7]);
    }
}

// ---------------------------------------------------------------------------
// Kernel 1: scores S = X X^T, lower-triangular tiles (compacted grid).
// ---------------------------------------------------------------------------
__global__ __launch_bounds__(TPB, 2) void gemm_scores(const float* __restrict__ x,
                                                      float* __restrict__ Sg) {
    const int b = blockIdx.y;
    // decode linear triangular index -> (it, jt), jt <= it
    const int t = blockIdx.x;
    int it = (int)((sqrtf(8.f * (float)t + 1.f) - 1.f) * 0.5f);
    while ((it + 1) * (it + 2) / 2 <= t) ++it;
    while (it * (it + 1) / 2 > t) --it;
    const int jt = t - it * (it + 1) / 2;

    extern __shared__ float sm[];
    float* AsBase = sm;                 // [2][BK][LDA]
    float* BsBase = sm + AS_FLOATS;     // [2][BK][LDB]

    const float* X = x + (size_t)b * SEQ * DIM;
    float* Sb = Sg + (size_t)b * SEQ * SEQ;

    const int tid = threadIdx.x;
    const int tm = tid / 16, tn = tid % 16;
    const int i0 = it * BM, j0 = jt * BN;
    const int lr = tid / 4, lc = (tid % 4) * 4;   // 128x16 tile: r=idx>>2, c4=(idx&3)*4

    Acc acc;
#pragma unroll
    for (int v = 0; v < 8; v++)
#pragma unroll
        for (int p = 0; p < 4; p++) acc.a[v][p] = 0ull;

    float4 a0, a1, b0, b1;
    auto ldg = [&](int k0) {
        a0 = *(const float4*)&X[(size_t)(i0 + lr)      * DIM + k0 + lc];
        a1 = *(const float4*)&X[(size_t)(i0 + lr + 64) * DIM + k0 + lc];
        b0 = *(const float4*)&X[(size_t)(j0 + lr)      * DIM + k0 + lc];
        b1 = *(const float4*)&X[(size_t)(j0 + lr + 64) * DIM + k0 + lc];
    };
    auto sts = [&](int s) {
        float* As = AsBase + s * BK * LDA;
        float* Bs = BsBase + s * BK * LDB;
        As[(lc + 0) * LDA + lr] = a0.x; As[(lc + 1) * LDA + lr] = a0.y;
        As[(lc + 2) * LDA + lr] = a0.z; As[(lc + 3) * LDA + lr] = a0.w;
        As[(lc + 0) * LDA + lr + 64] = a1.x; As[(lc + 1) * LDA + lr + 64] = a1.y;
        As[(lc + 2) * LDA + lr + 64] = a1.z; As[(lc + 3) * LDA + lr + 64] = a1.w;
        *(ull*)&Bs[(lc + 0) * LDB + 2 * lr] = dup2(b0.x);
        *(ull*)&Bs[(lc + 1) * LDB + 2 * lr] = dup2(b0.y);
        *(ull*)&Bs[(lc + 2) * LDB + 2 * lr] = dup2(b0.z);
        *(ull*)&Bs[(lc + 3) * LDB + 2 * lr] = dup2(b0.w);
        *(ull*)&Bs[(lc + 0) * LDB + 2 * (lr + 64)] = dup2(b1.x);
        *(ull*)&Bs[(lc + 1) * LDB + 2 * (lr + 64)] = dup2(b1.y);
        *(ull*)&Bs[(lc + 2) * LDB + 2 * (lr + 64)] = dup2(b1.z);
        *(ull*)&Bs[(lc + 3) * LDB + 2 * (lr + 64)] = dup2(b1.w);
    };

    const int NC = DIM / BK;
    ldg(0);
    sts(0);
    __syncthreads();
    for (int c = 0; c < NC; c++) {
        if (c + 1 < NC) ldg((c + 1) * BK);
        compute_chunk(AsBase + (c & 1) * BK * LDA, BsBase + (c & 1) * BK * LDB, tm, tn, acc);
        if (c + 1 < NC) sts((c + 1) & 1);
        __syncthreads();
    }
    store_tile(&Sb[(size_t)i0 * SEQ + j0], SEQ, tm, tn, acc);
}

// ---------------------------------------------------------------------------
// Kernel 2: softmax rows (strict-lower causal; row0 uniform 1/T), float4.
// ---------------------------------------------------------------------------
__global__ __launch_bounds__(256) void softmax_rows(float* __restrict__ Wg) {
    const int i = blockIdx.x, b = blockIdx.y;
    float* row = Wg + ((size_t)b * SEQ + i) * SEQ;
    const int tid = threadIdx.x;
    if (i == 0) {
        const float v = 1.0f / (float)SEQ;
        const float4 v4 = make_float4(v, v, v, v);
#pragma unroll
        for (int s = 0; s < 2; s++) *(float4*)&row[(tid + s * 256) * 4] = v4;
        return;
    }
    float vals[8];
    float m = -3.0e38f;
#pragma unroll
    for (int s = 0; s < 2; s++) {
        const int j4 = (tid + s * 256) * 4;
        if (j4 < i) {
            float4 v = *(const float4*)&row[j4];
            vals[s * 4 + 0] = (j4 + 0 < i) ? v.x : -3.0e38f;
            vals[s * 4 + 1] = (j4 + 1 < i) ? v.y : -3.0e38f;
            vals[s * 4 + 2] = (j4 + 2 < i) ? v.z : -3.0e38f;
            vals[s * 4 + 3] = (j4 + 3 < i) ? v.w : -3.0e38f;
        } else {
            vals[s * 4 + 0] = vals[s * 4 + 1] = vals[s * 4 + 2] = vals[s * 4 + 3] = -3.0e38f;
        }
#pragma unroll
        for (int e = 0; e < 4; e++) m = fmaxf(m, vals[s * 4 + e]);
    }
    __shared__ float sred[8];
#pragma unroll
    for (int o = 16; o; o >>= 1) m = fmaxf(m, __shfl_xor_sync(0xffffffffu, m, o));
    if ((tid & 31) == 0) sred[tid >> 5] = m;
    __syncthreads();
    m = sred[0];
#pragma unroll
    for (int w = 1; w < 8; w++) m = fmaxf(m, sred[w]);
    float l = 0.f;
#pragma unroll
    for (int s = 0; s < 8; s++) {
        float e = (vals[s] > -1.0e38f) ? __expf(vals[s] - m) : 0.f;
        vals[s] = e;
        l += e;
    }
#pragma unroll
    for (int o = 16; o; o >>= 1) l += __shfl_xor_sync(0xffffffffu, l, o);
    __syncthreads();
    if ((tid & 31) == 0) sred[tid >> 5] = l;
    __syncthreads();
    l = 0.f;
#pragma unroll
    for (int w = 0; w < 8; w++) l += sred[w];
    const float inv = 1.0f / l;
#pragma unroll
    for (int s = 0; s < 2; s++) {
        const int j4 = (tid + s * 256) * 4;
        *(float4*)&row[j4] = make_float4(vals[s * 4 + 0] * inv, vals[s * 4 + 1] * inv,
                                         vals[s * 4 + 2] * inv, vals[s * 4 + 3] * inv);
    }
}

// ---------------------------------------------------------------------------
// Kernel 3: O = W @ X, K bounded at (it+1)*BM (row 0 fixed later).
// ---------------------------------------------------------------------------
__global__ __launch_bounds__(TPB, 2) void gemm_av(const float* __restrict__ Wg,
                                                  const float* __restrict__ x,
                                                  float* __restrict__ Og) {
    const int b = blockIdx.z, it = blockIdx.y, dt = blockIdx.x;

    extern __shared__ float sm[];
    float* AsBase = sm;
    float* BsBase = sm + AS_FLOATS;

    const float* W = Wg + (size_t)b * SEQ * SEQ;
    const float* X = x + (size_t)b * SEQ * DIM;
    float* Ob = Og + (size_t)b * SEQ * DIM;

    const int tid = threadIdx.x;
    const int tm = tid / 16, tn = tid % 16;
    const int i0 = it * BM, d0 = dt * BN;

    const int lrA = tid / 4, lcA = (tid % 4) * 4;    // W tile 128x16
    const int krB = tid / 32, dcB = (tid % 32) * 4;  // X tile 16x128: 2 rows per thread step

    Acc acc;
#pragma unroll
    for (int v = 0; v < 8; v++)
#pragma unroll
        for (int p = 0; p < 4; p++) acc.a[v][p] = 0ull;

    float4 a0, a1, b0, b1;
    auto ldg = [&](int k0) {
        a0 = *(const float4*)&W[(size_t)(i0 + lrA)      * SEQ + k0 + lcA];
        a1 = *(const float4*)&W[(size_t)(i0 + lrA + 64) * SEQ + k0 + lcA];
        b0 = *(const float4*)&X[(size_t)(k0 + krB)     * DIM + d0 + dcB];
        b1 = *(const float4*)&X[(size_t)(k0 + krB + 8) * DIM + d0 + dcB];
    };
    auto sts = [&](int s) {
        float* As = AsBase + s * BK * LDA;
        float* Bs = BsBase + s * BK * LDB;
        As[(lcA + 0) * LDA + lrA] = a0.x; As[(lcA + 1) * LDA + lrA] = a0.y;
        As[(lcA + 2) * LDA + lrA] = a0.z; As[(lcA + 3) * LDA + lrA] = a0.w;
        As[(lcA + 0) * LDA + lrA + 64] = a1.x; As[(lcA + 1) * LDA + lrA + 64] = a1.y;
        As[(lcA + 2) * LDA + lrA + 64] = a1.z; As[(lcA + 3) * LDA + lrA + 64] = a1.w;
        *(ull*)&Bs[krB * LDB + 2 * (dcB + 0)] = dup2(b0.x);
        *(ull*)&Bs[krB * LDB + 2 * (dcB + 1)] = dup2(b0.y);
        *(ull*)&Bs[krB * LDB + 2 * (dcB + 2)] = dup2(b0.z);
        *(ull*)&Bs[krB * LDB + 2 * (dcB + 3)] = dup2(b0.w);
        *(ull*)&Bs[(krB + 8) * LDB + 2 * (dcB + 0)] = dup2(b1.x);
        *(ull*)&Bs[(krB + 8) * LDB + 2 * (dcB + 1)] = dup2(b1.y);
        *(ull*)&Bs[(krB + 8) * LDB + 2 * (dcB + 2)] = dup2(b1.z);
        *(ull*)&Bs[(krB + 8) * LDB + 2 * (dcB + 3)] = dup2(b1.w);
    };

    const int NC = (it + 1) * (BM / BK);   // causal K bound
    ldg(0);
    sts(0);
    __syncthreads();
    for (int c = 0; c < NC; c++) {
        if (c + 1 < NC) ldg((c + 1) * BK);
        compute_chunk(AsBase + (c & 1) * BK * LDA, BsBase + (c & 1) * BK * LDB, tm, tn, acc);
        if (c + 1 < NC) sts((c + 1) & 1);
        __syncthreads();
    }
    store_tile(&Ob[(size_t)i0 * DIM + d0], DIM, tm, tn, acc);
}

// ---------------------------------------------------------------------------
// Row 0: att_vec[b,0,:] = mean_j x[b,j,:]  (two-stage, 64 slices/batch)
// ---------------------------------------------------------------------------
__device__ float g_r0part[BATCH][64][DIM];

__global__ __launch_bounds__(256) void r0_partial(const float* __restrict__ x) {
    const int b = blockIdx.y, sl = blockIdx.x;
    const float* X = x + (size_t)b * SEQ * DIM;
    const int tid = threadIdx.x;
    float s[4] = {0.f, 0.f, 0.f, 0.f};
    const int j0 = sl * 32;
    for (int j = j0; j < j0 + 32; j++) {
#pragma unroll
        for (int q = 0; q < 4; q++) s[q] += X[(size_t)j * DIM + tid + q * 256];
    }
#pragma unroll
    for (int q = 0; q < 4; q++) g_r0part[b][sl][tid + q * 256] = s[q];
}

__global__ __launch_bounds__(256) void r0_reduce(float* __restrict__ Og) {
    const int b = blockIdx.y;
    const int d = blockIdx.x * 256 + threadIdx.x;
    float s = 0.f;
#pragma unroll
    for (int sl = 0; sl < 64; sl++) s += g_r0part[b][sl][d];
    Og[(size_t)b * SEQ * DIM + d] = s * (1.0f / (float)SEQ);
}

// ---------------------------------------------------------------------------
extern "C" void kernel_launch(void* const* d_in, const int* in_sizes, int n_in,
                              void* d_out, int out_size) {
    const float* x = (const float*)d_in[0];
    float* out     = (float*)d_out;
    float* att_vec = out;                                   // [B,T,D]
    float* Wg      = out + (size_t)BATCH * SEQ * DIM;       // [B,T,T]

    static int configured = 0;
    if (!configured) {
        cudaFuncSetAttribute(gemm_scores, cudaFuncAttributeMaxDynamicSharedMemorySize, GEMM_SMEM);
        cudaFuncSetAttribute(gemm_av, cudaFuncAttributeMaxDynamicSharedMemorySize, GEMM_SMEM);
        configured = 1;
    }

    const int NT = SEQ / BM;                  // 16
    dim3 g1(NT * (NT + 1) / 2, BATCH);        // 136 lower-tri tiles per batch
    gemm_scores<<<g1, TPB, GEMM_SMEM>>>(x, Wg);

    dim3 g2(SEQ, BATCH);
    softmax_rows<<<g2, 256>>>(Wg);

    dim3 g3(DIM / BN, SEQ / BM, BATCH);
    gemm_av<<<g3, TPB, GEMM_SMEM>>>(Wg, x, att_vec);

    dim3 g4(64, BATCH);
    r0_partial<<<g4, 256>>>(x);
    dim3 g5(DIM / 256, BATCH);
    r0_reduce<<<g5, 256>>>(att_vec);
}

// round 8
// speedup vs baseline: 3.2902x; 3.2902x over previous
#include <cuda_runtime.h>
#include <cstdint>

#define BATCH 8
#define SEQ   2048
#define DIM   1024

#define BM 128
#define BN 128
#define BK 16
#define TPB 256
#define LDR 132   // smem row stride (floats): 128 + 4 pad

typedef unsigned long long ull;

__device__ __forceinline__ void ffma2(ull& d, ull a, ull b) {
    asm("fma.rn.f32x2 %0, %1, %2, %0;" : "+l"(d) : "l"(a), "l"(b));
}
__device__ __forceinline__ ull dup2(float v) {
    ull r; asm("mov.b64 %0, {%1, %2};" : "=l"(r) : "f"(v), "f"(v)); return r;
}
__device__ __forceinline__ void unpk(ull p, float& lo, float& hi) {
    asm("mov.b64 {%0, %1}, %2;" : "=f"(lo), "=f"(hi) : "l"(p));
}

struct Acc {
    ull a[8][4];
};

// As/Bs: [BK][LDR], transposed tiles (row k, col m/n). B duplicated in registers.
__device__ __forceinline__ void compute_chunk(const float (*As)[LDR],
                                              const float (*Bs)[LDR],
                                              int tm, int tn, Acc& acc) {
#pragma unroll
    for (int k = 0; k < BK; k++) {
        ulonglong2 a01 = *(const ulonglong2*)&As[k][tm * 4];
        ulonglong2 a23 = *(const ulonglong2*)&As[k][64 + tm * 4];
        float4 b0 = *(const float4*)&Bs[k][tn * 4];
        float4 b1 = *(const float4*)&Bs[k][64 + tn * 4];
        ull ap[4] = {a01.x, a01.y, a23.x, a23.y};
        ull bd[8] = {dup2(b0.x), dup2(b0.y), dup2(b0.z), dup2(b0.w),
                     dup2(b1.x), dup2(b1.y), dup2(b1.z), dup2(b1.w)};
#pragma unroll
        for (int v = 0; v < 8; v++)
#pragma unroll
            for (int p = 0; p < 4; p++) ffma2(acc.a[v][p], ap[p], bd[v]);
    }
}

__device__ __forceinline__ void store_tile(float* dst, size_t ld, int tm, int tn,
                                           const Acc& acc) {
#pragma unroll
    for (int u = 0; u < 8; u++) {
        const int p = u >> 1, hi = u & 1;
        const int r = (u < 4) ? (tm * 4 + u) : (64 + tm * 4 + (u - 4));
        float c[8];
#pragma unroll
        for (int v = 0; v < 8; v++) {
            float lo, hh;
            unpk(acc.a[v][p], lo, hh);
            c[v] = hi ? hh : lo;
        }
        *(float4*)&dst[(size_t)r * ld + tn * 4]      = make_float4(c[0], c[1], c[2], c[3]);
        *(float4*)&dst[(size_t)r * ld + 64 + tn * 4] = make_float4(c[4], c[5], c[6], c[7]);
    }
}

// ---------------------------------------------------------------------------
// Kernel 1: scores S = X X^T, lower-triangular tiles (compacted grid).
// ---------------------------------------------------------------------------
__global__ __launch_bounds__(TPB, 2) void gemm_scores(const float* __restrict__ x,
                                                      float* __restrict__ Sg) {
    const int b = blockIdx.y;
    const int t = blockIdx.x;
    int it = (int)((sqrtf(8.f * (float)t + 1.f) - 1.f) * 0.5f);
    while ((it + 1) * (it + 2) / 2 <= t) ++it;
    while (it * (it + 1) / 2 > t) --it;
    const int jt = t - it * (it + 1) / 2;

    const float* X = x + (size_t)b * SEQ * DIM;
    float* Sb = Sg + (size_t)b * SEQ * SEQ;

    __shared__ float As[2][BK][LDR];
    __shared__ float Bs[2][BK][LDR];

    const int tid = threadIdx.x;
    const int tm = tid / 16, tn = tid % 16;
    const int i0 = it * BM, j0 = jt * BN;
    const int lr = tid / 4, lc = (tid % 4) * 4;

    Acc acc;
#pragma unroll
    for (int v = 0; v < 8; v++)
#pragma unroll
        for (int p = 0; p < 4; p++) acc.a[v][p] = 0ull;

    float4 a0, a1, b0, b1;
    auto ldg = [&](int k0) {
        a0 = *(const float4*)&X[(size_t)(i0 + lr)      * DIM + k0 + lc];
        a1 = *(const float4*)&X[(size_t)(i0 + lr + 64) * DIM + k0 + lc];
        b0 = *(const float4*)&X[(size_t)(j0 + lr)      * DIM + k0 + lc];
        b1 = *(const float4*)&X[(size_t)(j0 + lr + 64) * DIM + k0 + lc];
    };
    auto sts = [&](int s) {
        As[s][lc + 0][lr] = a0.x; As[s][lc + 1][lr] = a0.y;
        As[s][lc + 2][lr] = a0.z; As[s][lc + 3][lr] = a0.w;
        As[s][lc + 0][lr + 64] = a1.x; As[s][lc + 1][lr + 64] = a1.y;
        As[s][lc + 2][lr + 64] = a1.z; As[s][lc + 3][lr + 64] = a1.w;
        Bs[s][lc + 0][lr] = b0.x; Bs[s][lc + 1][lr] = b0.y;
        Bs[s][lc + 2][lr] = b0.z; Bs[s][lc + 3][lr] = b0.w;
        Bs[s][lc + 0][lr + 64] = b1.x; Bs[s][lc + 1][lr + 64] = b1.y;
        Bs[s][lc + 2][lr + 64] = b1.z; Bs[s][lc + 3][lr + 64] = b1.w;
    };

    const int NC = DIM / BK;
    ldg(0);
    sts(0);
    __syncthreads();
    for (int c = 0; c < NC; c++) {
        if (c + 1 < NC) ldg((c + 1) * BK);
        compute_chunk(As[c & 1], Bs[c & 1], tm, tn, acc);
        if (c + 1 < NC) sts((c + 1) & 1);
        __syncthreads();
    }
    store_tile(&Sb[(size_t)i0 * SEQ + j0], SEQ, tm, tn, acc);
}

// ---------------------------------------------------------------------------
// Kernel 2: softmax rows (strict-lower causal; row0 uniform 1/T), float4.
// ---------------------------------------------------------------------------
__global__ __launch_bounds__(256) void softmax_rows(float* __restrict__ Wg) {
    const int i = blockIdx.x, b = blockIdx.y;
    float* row = Wg + ((size_t)b * SEQ + i) * SEQ;
    const int tid = threadIdx.x;
    if (i == 0) {
        const float v = 1.0f / (float)SEQ;
        const float4 v4 = make_float4(v, v, v, v);
#pragma unroll
        for (int s = 0; s < 2; s++) *(float4*)&row[(tid + s * 256) * 4] = v4;
        return;
    }
    float vals[8];
    float m = -3.0e38f;
#pragma unroll
    for (int s = 0; s < 2; s++) {
        const int j4 = (tid + s * 256) * 4;
        if (j4 < i) {
            float4 v = *(const float4*)&row[j4];
            vals[s * 4 + 0] = (j4 + 0 < i) ? v.x : -3.0e38f;
            vals[s * 4 + 1] = (j4 + 1 < i) ? v.y : -3.0e38f;
            vals[s * 4 + 2] = (j4 + 2 < i) ? v.z : -3.0e38f;
            vals[s * 4 + 3] = (j4 + 3 < i) ? v.w : -3.0e38f;
        } else {
            vals[s * 4 + 0] = vals[s * 4 + 1] = vals[s * 4 + 2] = vals[s * 4 + 3] = -3.0e38f;
        }
#pragma unroll
        for (int e = 0; e < 4; e++) m = fmaxf(m, vals[s * 4 + e]);
    }
    __shared__ float sred[8];
#pragma unroll
    for (int o = 16; o; o >>= 1) m = fmaxf(m, __shfl_xor_sync(0xffffffffu, m, o));
    if ((tid & 31) == 0) sred[tid >> 5] = m;
    __syncthreads();
    m = sred[0];
#pragma unroll
    for (int w = 1; w < 8; w++) m = fmaxf(m, sred[w]);
    float l = 0.f;
#pragma unroll
    for (int s = 0; s < 8; s++) {
        float e = (vals[s] > -1.0e38f) ? __expf(vals[s] - m) : 0.f;
        vals[s] = e;
        l += e;
    }
#pragma unroll
    for (int o = 16; o; o >>= 1) l += __shfl_xor_sync(0xffffffffu, l, o);
    __syncthreads();
    if ((tid & 31) == 0) sred[tid >> 5] = l;
    __syncthreads();
    l = 0.f;
#pragma unroll
    for (int w = 0; w < 8; w++) l += sred[w];
    const float inv = 1.0f / l;
#pragma unroll
    for (int s = 0; s < 2; s++) {
        const int j4 = (tid + s * 256) * 4;
        *(float4*)&row[j4] = make_float4(vals[s * 4 + 0] * inv, vals[s * 4 + 1] * inv,
                                         vals[s * 4 + 2] * inv, vals[s * 4 + 3] * inv);
    }
}

// ---------------------------------------------------------------------------
// Kernel 3: O = W @ X, K bounded at (it+1)*BM; heavy tiles scheduled first.
// ---------------------------------------------------------------------------
__global__ __launch_bounds__(TPB, 2) void gemm_av(const float* __restrict__ Wg,
                                                  const float* __restrict__ x,
                                                  float* __restrict__ Og) {
    const int b = blockIdx.z, dt = blockIdx.x;
    const int it = (SEQ / BM - 1) - blockIdx.y;   // heavy-first ordering

    const float* W = Wg + (size_t)b * SEQ * SEQ;
    const float* X = x + (size_t)b * SEQ * DIM;
    float* Ob = Og + (size_t)b * SEQ * DIM;

    __shared__ float As[2][BK][LDR];
    __shared__ float Bs[2][BK][LDR];

    const int tid = threadIdx.x;
    const int tm = tid / 16, tn = tid % 16;
    const int i0 = it * BM, d0 = dt * BN;

    const int lrA = tid / 4, lcA = (tid % 4) * 4;
    const int lrB = tid / 32, lcB = (tid % 32) * 4;

    Acc acc;
#pragma unroll
    for (int v = 0; v < 8; v++)
#pragma unroll
        for (int p = 0; p < 4; p++) acc.a[v][p] = 0ull;

    float4 a0, a1, b0, b1;
    auto ldg = [&](int k0) {
        a0 = *(const float4*)&W[(size_t)(i0 + lrA)      * SEQ + k0 + lcA];
        a1 = *(const float4*)&W[(size_t)(i0 + lrA + 64) * SEQ + k0 + lcA];
        b0 = *(const float4*)&X[(size_t)(k0 + lrB)     * DIM + d0 + lcB];
        b1 = *(const float4*)&X[(size_t)(k0 + lrB + 8) * DIM + d0 + lcB];
    };
    auto sts = [&](int s) {
        As[s][lcA + 0][lrA] = a0.x; As[s][lcA + 1][lrA] = a0.y;
        As[s][lcA + 2][lrA] = a0.z; As[s][lcA + 3][lrA] = a0.w;
        As[s][lcA + 0][lrA + 64] = a1.x; As[s][lcA + 1][lrA + 64] = a1.y;
        As[s][lcA + 2][lrA + 64] = a1.z; As[s][lcA + 3][lrA + 64] = a1.w;
        *(float4*)&Bs[s][lrB][lcB]     = b0;
        *(float4*)&Bs[s][lrB + 8][lcB] = b1;
    };

    const int NC = (it + 1) * (BM / BK);   // causal K bound
    ldg(0);
    sts(0);
    __syncthreads();
    for (int c = 0; c < NC; c++) {
        if (c + 1 < NC) ldg((c + 1) * BK);
        compute_chunk(As[c & 1], Bs[c & 1], tm, tn, acc);
        if (c + 1 < NC) sts((c + 1) & 1);
        __syncthreads();
    }
    store_tile(&Ob[(size_t)i0 * DIM + d0], DIM, tm, tn, acc);
}

// ---------------------------------------------------------------------------
// Row 0: att_vec[b,0,:] = mean_j x[b,j,:]  (two-stage, 64 slices/batch)
// ---------------------------------------------------------------------------
__device__ float g_r0part[BATCH][64][DIM];

__global__ __launch_bounds__(256) void r0_partial(const float* __restrict__ x) {
    const int b = blockIdx.y, sl = blockIdx.x;
    const float* X = x + (size_t)b * SEQ * DIM;
    const int tid = threadIdx.x;
    float s[4] = {0.f, 0.f, 0.f, 0.f};
    const int j0 = sl * 32;
    for (int j = j0; j < j0 + 32; j++) {
#pragma unroll
        for (int q = 0; q < 4; q++) s[q] += X[(size_t)j * DIM + tid + q * 256];
    }
#pragma unroll
    for (int q = 0; q < 4; q++) g_r0part[b][sl][tid + q * 256] = s[q];
}

__global__ __launch_bounds__(256) void r0_reduce(float* __restrict__ Og) {
    const int b = blockIdx.y;
    const int d = blockIdx.x * 256 + threadIdx.x;
    float s = 0.f;
#pragma unroll
    for (int sl = 0; sl < 64; sl++) s += g_r0part[b][sl][d];
    Og[(size_t)b * SEQ * DIM + d] = s * (1.0f / (float)SEQ);
}

// ---------------------------------------------------------------------------
extern "C" void kernel_launch(void* const* d_in, const int* in_sizes, int n_in,
                              void* d_out, int out_size) {
    const float* x = (const float*)d_in[0];
    float* out     = (float*)d_out;
    float* att_vec = out;                                   // [B,T,D]
    float* Wg      = out + (size_t)BATCH * SEQ * DIM;       // [B,T,T]

    const int NT = SEQ / BM;                  // 16
    dim3 g1(NT * (NT + 1) / 2, BATCH);        // 136 lower-tri tiles per batch
    gemm_scores<<<g1, TPB>>>(x, Wg);

    dim3 g2(SEQ, BATCH);
    softmax_rows<<<g2, 256>>>(Wg);

    dim3 g3(DIM / BN, SEQ / BM, BATCH);
    gemm_av<<<g3, TPB>>>(Wg, x, att_vec);

    dim3 g4(64, BATCH);
    r0_partial<<<g4, 256>>>(x);
    dim3 g5(DIM / 256, BATCH);
    r0_reduce<<<g5, 256>>>(att_vec);
}